// round 7
// baseline (speedup 1.0000x reference)
#include <cuda_runtime.h>
#include <cstdint>

#define N_NODES 500000
#define N_EDGES 16000000
#define IN_DIM 17
#define NPB 512              // nodes per block in node_prep

// __align__(16): finalize reads these with 16B/8B vector loads.
__device__ __align__(16) unsigned long long g_acc[N_NODES];  // [16:64)=fix2^-32 sum, [0:16)=count
__device__ __align__(16) float g_base[N_NODES];   // b_l + x . w_r
__device__ float g_proj[N_NODES];                 // x . w_l

#define FIX_SCALE 4294967296.0f
#define INV_FIX_SCALE 2.3283064365386963e-10f

// ---------------------------------------------------------------------------
// Kernel 1: node projection + acc zeroing. 512 nodes/block, 2 nodes/thread,
// single barrier; float4-coalesced smem stage.
// ---------------------------------------------------------------------------
__global__ void __launch_bounds__(256) node_prep(
    const float* __restrict__ x,
    const float* __restrict__ w_l,
    const float* __restrict__ b_l,
    const float* __restrict__ w_r)
{
    __shared__ float sx[NPB * IN_DIM];          // 34816 B
    __shared__ float swl[IN_DIM], swr[IN_DIM];

    int base = blockIdx.x * NPB;
    int nblk = N_NODES - base; if (nblk > NPB) nblk = NPB;

    if (threadIdx.x < IN_DIM) {
        swl[threadIdx.x] = w_l[threadIdx.x];
        swr[threadIdx.x] = w_r[threadIdx.x];
    }

    const float* xb = x + (size_t)base * IN_DIM;
    if (nblk == NPB) {
        // NPB*17 = 8704 floats = 2176 float4; tile start 16B-aligned (34816*bid).
        const float4* x4 = (const float4*)xb;
        float4* s4 = (float4*)sx;
#pragma unroll
        for (int i = threadIdx.x; i < (NPB * IN_DIM) / 4; i += 256)
            s4[i] = __ldg(&x4[i]);
    } else {
        for (int i = threadIdx.x; i < nblk * IN_DIM; i += 256)
            sx[i] = xb[i];
    }
    __syncthreads();

    float blv = __ldg(b_l);
#pragma unroll
    for (int half = 0; half < 2; half++) {
        int local = threadIdx.x + half * 256;
        int n = base + local;
        if (local < nblk) {
            const float* row = sx + local * IN_DIM;
            float pl = 0.f, pr = 0.f;
#pragma unroll
            for (int i = 0; i < IN_DIM; i++) {
                float v = row[i];
                pl = fmaf(v, swl[i], pl);
                pr = fmaf(v, swr[i], pr);
            }
            g_proj[n] = pl;
            g_base[n] = pr + blv;
            g_acc[n]  = 0ull;
        }
    }
}

// ---------------------------------------------------------------------------
// Kernel 2: edge scatter. 16 edges/thread; front-batched int4 index loads
// (__ldcs evict-first), divergent proj gathers, one u64 RED per edge.
// ---------------------------------------------------------------------------
__device__ __forceinline__ void red_edge(int dst, float m)
{
    long long pkt = ((long long)llrintf(m * FIX_SCALE) << 16) | 1ll;
    asm volatile("red.global.add.u64 [%0], %1;"
                 :: "l"(&g_acc[dst]), "l"(pkt) : "memory");
}

__global__ void __launch_bounds__(256) edge_scatter(const int* __restrict__ ei)
{
    const int4* __restrict__ srcv = (const int4*)ei;
    const int4* __restrict__ dstv = (const int4*)(ei + N_EDGES);
    int i = blockIdx.x * blockDim.x + threadIdx.x;
    if (i >= N_EDGES / 16) return;

    int4 s[4], d[4];
#pragma unroll
    for (int k = 0; k < 4; k++) s[k] = __ldcs(&srcv[4 * i + k]);
#pragma unroll
    for (int k = 0; k < 4; k++) d[k] = __ldcs(&dstv[4 * i + k]);

    float m[16];
#pragma unroll
    for (int k = 0; k < 4; k++) {
        m[4 * k + 0] = __ldg(&g_proj[s[k].x]);
        m[4 * k + 1] = __ldg(&g_proj[s[k].y]);
        m[4 * k + 2] = __ldg(&g_proj[s[k].z]);
        m[4 * k + 3] = __ldg(&g_proj[s[k].w]);
    }
#pragma unroll
    for (int k = 0; k < 4; k++) {
        red_edge(d[k].x, m[4 * k + 0]);
        red_edge(d[k].y, m[4 * k + 1]);
        red_edge(d[k].z, m[4 * k + 2]);
        red_edge(d[k].w, m[4 * k + 3]);
    }
}

// ---------------------------------------------------------------------------
// Kernel 3: finalize, 2 nodes/thread with vector loads.
// ---------------------------------------------------------------------------
__global__ void __launch_bounds__(256) finalize(
    float* __restrict__ out,
    const float* __restrict__ w_o,
    const float* __restrict__ b_o)
{
    int t = blockIdx.x * blockDim.x + threadIdx.x;
    float wo = __ldg(w_o), bo = __ldg(b_o);

    int n0 = 2 * t;
    if (n0 + 1 < N_NODES) {
        ulonglong2 p2 = *(const ulonglong2*)&g_acc[n0];
        float2 b2 = *(const float2*)&g_base[n0];
        float2 o;
        {
            long long p = (long long)p2.x;
            int cnt = (int)(p & 0xFFFFll);
            float sum = (float)((p - (long long)cnt) >> 16) * INV_FIX_SCALE;
            float h = sum / fmaxf((float)cnt, 1.0f) + b2.x;
            h = (h > 0.f) ? h : expm1f(h);
            o.x = fmaf(h, wo, bo);
        }
        {
            long long p = (long long)p2.y;
            int cnt = (int)(p & 0xFFFFll);
            float sum = (float)((p - (long long)cnt) >> 16) * INV_FIX_SCALE;
            float h = sum / fmaxf((float)cnt, 1.0f) + b2.y;
            h = (h > 0.f) ? h : expm1f(h);
            o.y = fmaf(h, wo, bo);
        }
        *(float2*)&out[n0] = o;
    } else if (n0 < N_NODES) {
        long long p = (long long)g_acc[n0];
        int cnt = (int)(p & 0xFFFFll);
        float sum = (float)((p - (long long)cnt) >> 16) * INV_FIX_SCALE;
        float h = sum / fmaxf((float)cnt, 1.0f) + g_base[n0];
        h = (h > 0.f) ? h : expm1f(h);
        out[n0] = fmaf(h, wo, bo);
    }
}

extern "C" void kernel_launch(void* const* d_in, const int* in_sizes, int n_in,
                              void* d_out, int out_size)
{
    const float* x    = (const float*)d_in[0];
    const int*   ei   = (const int*)d_in[1];
    // d_in[2] = edge_weight: unused (faithful to reference / PyG SAGEConv)
    const float* w_l  = (const float*)d_in[3];
    const float* b_l  = (const float*)d_in[4];
    const float* w_r  = (const float*)d_in[5];
    const float* w_o  = (const float*)d_in[6];
    const float* b_o  = (const float*)d_in[7];
    float*       out  = (float*)d_out;

    (void)in_sizes; (void)n_in; (void)out_size;

    node_prep<<<(N_NODES + NPB - 1) / NPB, 256>>>(x, w_l, b_l, w_r);
    edge_scatter<<<(N_EDGES / 16 + 255) / 256, 256>>>(ei);
    finalize<<<(N_NODES / 2 + 255) / 256, 256>>>(out, w_o, b_o);
}